// round 6
// baseline (speedup 1.0000x reference)
#include <cuda_runtime.h>
#include <math.h>

#define N_NODES 50000
#define E_EDGES 800000
#define E_TOT   (E_EDGES + N_NODES)   // 850000 with self loops
#define F_IN    128
#define SLOPE   0.2f

// ---------------- scratch (static __device__ — no allocation) ----------------
__device__ float g_h[N_NODES * 128];        // transformed features
__device__ float g_o[N_NODES * 128];        // aggregated output
__device__ float g_als[N_NODES * 4];
__device__ float g_ald[N_NODES * 4];
__device__ float g_p[E_TOT * 4];            // exp(e) per edge (CSR order)
__device__ int   g_cnt[N_NODES];
__device__ int   g_off[N_NODES + 1];
__device__ int   g_cur[N_NODES];
__device__ int   g_csrc[E_TOT];

// ---------------- side stream for CSR/GEMM overlap ----------------
struct SideStream {
    cudaStream_t s;
    cudaEvent_t fork, join;
    SideStream() {
        cudaStreamCreateWithFlags(&s, cudaStreamNonBlocking);
        cudaEventCreateWithFlags(&fork, cudaEventDisableTiming);
        cudaEventCreateWithFlags(&join, cudaEventDisableTiming);
    }
};
static SideStream g_ss;

// ---------------- f32x2 helpers (sm_103a FFMA2) ----------------
__device__ __forceinline__ unsigned long long pack2(float lo, float hi) {
    unsigned long long r;
    asm("mov.b64 %0, {%1, %2};" : "=l"(r) : "f"(lo), "f"(hi));
    return r;
}
__device__ __forceinline__ void unpack2(unsigned long long v, float& lo, float& hi) {
    asm("mov.b64 {%0, %1}, %2;" : "=f"(lo), "=f"(hi) : "l"(v));
}
__device__ __forceinline__ unsigned long long ffma2(unsigned long long a,
                                                    unsigned long long b,
                                                    unsigned long long c) {
    unsigned long long d;
    asm("fma.rn.f32x2 %0, %1, %2, %3;" : "=l"(d) : "l"(a), "l"(b), "l"(c));
    return d;
}
__device__ __forceinline__ unsigned long long lds_b64(unsigned int addr) {
    unsigned long long v;
    asm volatile("ld.shared.b64 %0, [%1];" : "=l"(v) : "r"(addr));
    return v;
}
__device__ __forceinline__ unsigned int smem_u32(const void* p) {
    unsigned int a;
    asm("{ .reg .u64 t; cvta.to.shared.u64 t, %1; cvt.u32.u64 %0, t; }"
        : "=r"(a) : "l"(p));
    return a;
}

// ---------------- CSR build ----------------
__global__ void zero_int_kernel(int* p, int n) {
    int i = blockIdx.x * blockDim.x + threadIdx.x;
    if (i < n) p[i] = 0;
}

__global__ void hist_kernel(const int* __restrict__ ei, int* __restrict__ cnt) {
    int e = blockIdx.x * blockDim.x + threadIdx.x;
    if (e >= E_TOT) return;
    int d = (e < E_EDGES) ? ei[E_EDGES + e] : (e - E_EDGES);
    atomicAdd(&cnt[d], 1);
}

__global__ void scan_kernel(const int* __restrict__ cnt,
                            int* __restrict__ offsets,
                            int* __restrict__ cursor) {
    __shared__ int part[1024];
    const int T = 1024;
    const int C = (N_NODES + T - 1) / T;   // 49
    int t = threadIdx.x;
    int lo = t * C;
    int hi = lo + C; if (hi > N_NODES) hi = N_NODES;
    int s = 0;
    for (int i = lo; i < hi; i++) s += cnt[i];
    part[t] = s;
    __syncthreads();
    for (int off = 1; off < T; off <<= 1) {
        int v = (t >= off) ? part[t - off] : 0;
        __syncthreads();
        part[t] += v;
        __syncthreads();
    }
    int run = (t > 0) ? part[t - 1] : 0;   // exclusive base
    for (int i = lo; i < hi; i++) {
        offsets[i] = run;
        cursor[i]  = run;
        run += cnt[i];
    }
    if (t == 0) offsets[N_NODES] = E_TOT;
}

__global__ void scatter_kernel(const int* __restrict__ ei,
                               int* __restrict__ cursor,
                               int* __restrict__ csr_src) {
    int e = blockIdx.x * blockDim.x + threadIdx.x;
    if (e >= E_TOT) return;
    int s, d;
    if (e < E_EDGES) { s = ei[e]; d = ei[E_EDGES + e]; }
    else             { s = d = e - E_EDGES; }
    int pos = atomicAdd(&cursor[d], 1);
    csr_src[pos] = s;
}

// ---------------- GEMM (FFMA2): H = act(X + bias) @ W ----------------
// X staged transposed in smem (xsT[k][r], float stride 66 so row pairs are
// 8B-aligned). Warp-uniform LDS.64 broadcasts a row-pair; weights duplicated
// into both f32x2 lanes; 2 output columns per thread (col, col+MO/2).
template<int MO>
__global__ void __launch_bounds__(256)
gemm_kernel(const float* __restrict__ X,
            const float* __restrict__ W,
            const float* __restrict__ bias,
            float* __restrict__ Hout) {
    constexpr int RT = 64;                 // rows per block
    constexpr int HALF = MO / 2;
    constexpr int GROUPS = 256 / HALF;     // 4 (MO=128) / 8 (MO=64)
    constexpr int ROWS = RT / GROUPS;      // 16 / 8
    constexpr int PAIRS = ROWS / 2;        // 8 / 4
    constexpr int KSTRIDE = 66;            // floats per k row (even, pairs aligned)
    __shared__ float xsT[F_IN * KSTRIDE];

    const int row0 = blockIdx.x * RT;
    const int t = threadIdx.x;

    // ---- load X tile, store transposed ----
#pragma unroll
    for (int it = 0; it < 8; it++) {
        int idx = t + it * 256;            // 0..2047
        int r  = idx >> 5;                 // 0..63
        int k4 = idx & 31;
        int n  = row0 + r;
        float4 v = make_float4(0.f, 0.f, 0.f, 0.f);
        if (n < N_NODES) {
            v = reinterpret_cast<const float4*>(X)[n * 32 + k4];
            if (bias) {
                float4 b = reinterpret_cast<const float4*>(bias)[k4];
                v.x = fmaxf(v.x + b.x, 0.f);
                v.y = fmaxf(v.y + b.y, 0.f);
                v.z = fmaxf(v.z + b.z, 0.f);
                v.w = fmaxf(v.w + b.w, 0.f);
            }
        }
        xsT[(4 * k4 + 0) * KSTRIDE + r] = v.x;
        xsT[(4 * k4 + 1) * KSTRIDE + r] = v.y;
        xsT[(4 * k4 + 2) * KSTRIDE + r] = v.z;
        xsT[(4 * k4 + 3) * KSTRIDE + r] = v.w;
    }
    __syncthreads();

    const int col = t % HALF;              // this thread: cols col, col+HALF
    const int g   = t / HALF;
    const unsigned int sbase = smem_u32(xsT) + (unsigned)(g * ROWS) * 4u;

    unsigned long long accA[PAIRS], accB[PAIRS];
#pragma unroll
    for (int p = 0; p < PAIRS; p++) { accA[p] = 0ull; accB[p] = 0ull; }

    for (int k4 = 0; k4 < F_IN / 4; k4++) {
        unsigned long long wpa[4], wpb[4];
#pragma unroll
        for (int j = 0; j < 4; j++) {
            float wa = W[(k4 * 4 + j) * MO + col];
            float wb = W[(k4 * 4 + j) * MO + col + HALF];
            wpa[j] = pack2(wa, wa);
            wpb[j] = pack2(wb, wb);
        }
#pragma unroll
        for (int j = 0; j < 4; j++) {
            unsigned int ka = sbase + (unsigned)((k4 * 4 + j) * KSTRIDE) * 4u;
#pragma unroll
            for (int p = 0; p < PAIRS; p++) {
                unsigned long long xv = lds_b64(ka + 8u * p);  // rows 2p,2p+1
                accA[p] = ffma2(xv, wpa[j], accA[p]);
                accB[p] = ffma2(xv, wpb[j], accB[p]);
            }
        }
    }

#pragma unroll
    for (int p = 0; p < PAIRS; p++) {
        float a0, a1, b0, b1;
        unpack2(accA[p], a0, a1);
        unpack2(accB[p], b0, b1);
        int n0 = row0 + g * ROWS + 2 * p;
        if (n0 < N_NODES) {
            Hout[n0 * MO + col]        = a0;
            Hout[n0 * MO + col + HALF] = b0;
        }
        if (n0 + 1 < N_NODES) {
            Hout[(n0 + 1) * MO + col]        = a1;
            Hout[(n0 + 1) * MO + col + HALF] = b1;
        }
    }
}

// ---------------- attention coefficients ----------------
template<int H, int F>
__global__ void coef_kernel(const float* __restrict__ Hfeat,
                            const float* __restrict__ a_src,
                            const float* __restrict__ a_dst,
                            float* __restrict__ als, float* __restrict__ ald) {
    int i = blockIdx.x * blockDim.x + threadIdx.x;   // n*H + h
    if (i >= N_NODES * H) return;
    int n = i / H, h = i % H;
    const float* hp = Hfeat + n * (H * F) + h * F;
    const float* as = a_src + h * F;
    const float* ad = a_dst + h * F;
    float s = 0.f, d = 0.f;
#pragma unroll 8
    for (int f = 0; f < F; f++) {
        float v = hp[f];
        s = fmaf(v, as[f], s);
        d = fmaf(v, ad[f], d);
    }
    als[i] = s;
    ald[i] = d;
}

// ---------------- fused attention softmax + gather (H=4, F=32) ----------------
__global__ void gather4_kernel(const int* __restrict__ offsets,
                               const int* __restrict__ csr_src,
                               const float* __restrict__ als,
                               const float* __restrict__ ald,
                               const float* __restrict__ Hfeat,
                               float4* __restrict__ p_csr,
                               float* __restrict__ O) {
    int warp = (blockIdx.x * blockDim.x + threadIdx.x) >> 5;
    int lane = threadIdx.x & 31;
    if (warp >= N_NODES) return;
    const int d = warp;
    const int start = offsets[d], end = offsets[d + 1];

    float4 aldv = reinterpret_cast<const float4*>(ald)[d];
    float dx = 0.f, dy = 0.f, dz = 0.f, dw = 0.f;
    for (int j = start + lane; j < end; j += 32) {
        int s = csr_src[j];
        float4 a = reinterpret_cast<const float4*>(als)[s];
        float ex = a.x + aldv.x; ex = (ex > 0.f) ? ex : SLOPE * ex; ex = __expf(ex);
        float ey = a.y + aldv.y; ey = (ey > 0.f) ? ey : SLOPE * ey; ey = __expf(ey);
        float ez = a.z + aldv.z; ez = (ez > 0.f) ? ez : SLOPE * ez; ez = __expf(ez);
        float ew = a.w + aldv.w; ew = (ew > 0.f) ? ew : SLOPE * ew; ew = __expf(ew);
        p_csr[j] = make_float4(ex, ey, ez, ew);
        dx += ex; dy += ey; dz += ez; dw += ew;
    }
#pragma unroll
    for (int o = 16; o > 0; o >>= 1) {
        dx += __shfl_xor_sync(0xffffffffu, dx, o);
        dy += __shfl_xor_sync(0xffffffffu, dy, o);
        dz += __shfl_xor_sync(0xffffffffu, dz, o);
        dw += __shfl_xor_sync(0xffffffffu, dw, o);
    }
    const int h = lane >> 3;                       // head for this lane's float4
    float den = (h == 0) ? dx : (h == 1) ? dy : (h == 2) ? dz : dw;
    float invd = __fdividef(1.f, den);

    const float* ps = reinterpret_cast<const float*>(p_csr);
    float4 acc = make_float4(0.f, 0.f, 0.f, 0.f);
#pragma unroll 4
    for (int j = start; j < end; j++) {
        int s = csr_src[j];                        // broadcast
        float alpha = ps[j * 4 + h] * invd;
        float4 hv = reinterpret_cast<const float4*>(Hfeat)[s * 32 + lane];
        acc.x = fmaf(hv.x, alpha, acc.x);
        acc.y = fmaf(hv.y, alpha, acc.y);
        acc.z = fmaf(hv.z, alpha, acc.z);
        acc.w = fmaf(hv.w, alpha, acc.w);
    }
    reinterpret_cast<float4*>(O)[d * 32 + lane] = acc;
}

// ---------------- fused attention softmax + gather (H=1, F=64) ----------------
__global__ void gather1_kernel(const int* __restrict__ offsets,
                               const int* __restrict__ csr_src,
                               const float* __restrict__ als,
                               const float* __restrict__ ald,
                               const float* __restrict__ Hfeat,
                               float* __restrict__ p_csr,
                               float* __restrict__ O) {
    int warp = (blockIdx.x * blockDim.x + threadIdx.x) >> 5;
    int lane = threadIdx.x & 31;
    if (warp >= N_NODES) return;
    const int d = warp;
    const int start = offsets[d], end = offsets[d + 1];

    float aldd = ald[d];
    float den = 0.f;
    for (int j = start + lane; j < end; j += 32) {
        int s = csr_src[j];
        float e = als[s] + aldd;
        e = (e > 0.f) ? e : SLOPE * e;
        e = __expf(e);
        p_csr[j] = e;
        den += e;
    }
#pragma unroll
    for (int o = 16; o > 0; o >>= 1) den += __shfl_xor_sync(0xffffffffu, den, o);
    float invd = __fdividef(1.f, den);

    float2 acc = make_float2(0.f, 0.f);
#pragma unroll 4
    for (int j = start; j < end; j++) {
        int s = csr_src[j];
        float alpha = p_csr[j] * invd;
        float2 hv = reinterpret_cast<const float2*>(Hfeat)[s * 32 + lane];
        acc.x = fmaf(hv.x, alpha, acc.x);
        acc.y = fmaf(hv.y, alpha, acc.y);
    }
    reinterpret_cast<float2*>(O)[d * 32 + lane] = acc;
}

// ---------------- final: log_softmax(O + b3) over 64 classes ----------------
__global__ void final_kernel(const float* __restrict__ O,
                             const float* __restrict__ b3,
                             float* __restrict__ out) {
    int warp = (blockIdx.x * blockDim.x + threadIdx.x) >> 5;
    int lane = threadIdx.x & 31;
    if (warp >= N_NODES) return;
    const float* row = O + warp * 64;
    float v0 = row[lane]      + b3[lane];
    float v1 = row[32 + lane] + b3[32 + lane];
    float mx = fmaxf(v0, v1);
#pragma unroll
    for (int o = 16; o > 0; o >>= 1) mx = fmaxf(mx, __shfl_xor_sync(0xffffffffu, mx, o));
    float se = expf(v0 - mx) + expf(v1 - mx);
#pragma unroll
    for (int o = 16; o > 0; o >>= 1) se += __shfl_xor_sync(0xffffffffu, se, o);
    float lse = mx + logf(se);
    out[warp * 64 + lane]      = v0 - lse;
    out[warp * 64 + 32 + lane] = v1 - lse;
}

// ---------------- launcher ----------------
extern "C" void kernel_launch(void* const* d_in, const int* in_sizes, int n_in,
                              void* d_out, int out_size) {
    const float* x   = (const float*)d_in[0];
    const int*   ei  = (const int*)  d_in[1];
    const float* w1  = (const float*)d_in[2];
    const float* as1 = (const float*)d_in[3];
    const float* ad1 = (const float*)d_in[4];
    const float* b1  = (const float*)d_in[5];
    const float* w2  = (const float*)d_in[6];
    const float* as2 = (const float*)d_in[7];
    const float* ad2 = (const float*)d_in[8];
    const float* b2  = (const float*)d_in[9];
    const float* w3  = (const float*)d_in[10];
    const float* as3 = (const float*)d_in[11];
    const float* ad3 = (const float*)d_in[12];
    const float* b3  = (const float*)d_in[13];
    float* out = (float*)d_out;

    float *hbuf, *obuf, *als, *ald, *pbuf;
    int *cnt, *off, *cur, *csrc;
    cudaGetSymbolAddress((void**)&hbuf, g_h);
    cudaGetSymbolAddress((void**)&obuf, g_o);
    cudaGetSymbolAddress((void**)&als,  g_als);
    cudaGetSymbolAddress((void**)&ald,  g_ald);
    cudaGetSymbolAddress((void**)&pbuf, g_p);
    cudaGetSymbolAddress((void**)&cnt,  g_cnt);
    cudaGetSymbolAddress((void**)&off,  g_off);
    cudaGetSymbolAddress((void**)&cur,  g_cur);
    cudaGetSymbolAddress((void**)&csrc, g_csrc);

    auto cdiv = [](long long a, long long b) { return (int)((a + b - 1) / b); };

    const int gatherGrid = cdiv((long long)N_NODES * 32, 256);
    const int gemmGrid = cdiv(N_NODES, 64);

    // ---- fork: CSR build on side stream, concurrent with layer-1 GEMM+coef ----
    cudaEventRecord(g_ss.fork, 0);
    cudaStreamWaitEvent(g_ss.s, g_ss.fork, 0);
    zero_int_kernel<<<cdiv(N_NODES, 256), 256, 0, g_ss.s>>>(cnt, N_NODES);
    hist_kernel<<<cdiv(E_TOT, 256), 256, 0, g_ss.s>>>(ei, cnt);
    scan_kernel<<<1, 1024, 0, g_ss.s>>>(cnt, off, cur);
    scatter_kernel<<<cdiv(E_TOT, 256), 256, 0, g_ss.s>>>(ei, cur, csrc);
    cudaEventRecord(g_ss.join, g_ss.s);

    // ---- layer 1 (main stream, overlaps CSR build) ----
    gemm_kernel<128><<<gemmGrid, 256>>>(x, w1, nullptr, hbuf);
    coef_kernel<4, 32><<<cdiv(N_NODES * 4, 256), 256>>>(hbuf, as1, ad1, als, ald);
    cudaStreamWaitEvent(0, g_ss.join, 0);          // join before gather
    gather4_kernel<<<gatherGrid, 256>>>(off, csrc, als, ald, hbuf,
                                        (float4*)pbuf, obuf);

    // ---- layer 2 ----
    gemm_kernel<128><<<gemmGrid, 256>>>(obuf, w2, b1, hbuf);
    coef_kernel<4, 32><<<cdiv(N_NODES * 4, 256), 256>>>(hbuf, as2, ad2, als, ald);
    gather4_kernel<<<gatherGrid, 256>>>(off, csrc, als, ald, hbuf,
                                        (float4*)pbuf, obuf);

    // ---- layer 3 ----
    gemm_kernel<64><<<gemmGrid, 256>>>(obuf, w3, b2, hbuf);
    coef_kernel<1, 64><<<cdiv(N_NODES, 256), 256>>>(hbuf, as3, ad3, als, ald);
    gather1_kernel<<<gatherGrid, 256>>>(off, csrc, als, ald, hbuf, pbuf, obuf);

    // ---- log_softmax ----
    final_kernel<<<gatherGrid, 256>>>(obuf, b3, out);
}

// round 7
// speedup vs baseline: 1.4813x; 1.4813x over previous
#include <cuda_runtime.h>
#include <math.h>

#define N_NODES 50000
#define E_EDGES 800000
#define E_TOT   (E_EDGES + N_NODES)   // 850000 with self loops
#define F_IN    128
#define SLOPE   0.2f

// ---------------- scratch (static __device__ — no allocation) ----------------
__device__ float g_h[N_NODES * 128];        // transformed features
__device__ float g_o[N_NODES * 128];        // aggregated output
__device__ float g_als[N_NODES * 4];
__device__ float g_ald[N_NODES * 4];
__device__ float g_p[E_TOT * 4];            // exp(e) per edge (CSR order)
__device__ int   g_cnt[N_NODES];
__device__ int   g_off[N_NODES + 1];
__device__ int   g_cur[N_NODES];
__device__ int   g_csrc[E_TOT];

// ---------------- side stream for CSR/GEMM overlap ----------------
struct SideStream {
    cudaStream_t s;
    cudaEvent_t fork, join;
    SideStream() {
        cudaStreamCreateWithFlags(&s, cudaStreamNonBlocking);
        cudaEventCreateWithFlags(&fork, cudaEventDisableTiming);
        cudaEventCreateWithFlags(&join, cudaEventDisableTiming);
    }
};
static SideStream g_ss;

// ---------------- CSR build ----------------
__global__ void zero_int_kernel(int* p, int n) {
    int i = blockIdx.x * blockDim.x + threadIdx.x;
    if (i < n) p[i] = 0;
}

__global__ void hist_kernel(const int* __restrict__ ei, int* __restrict__ cnt) {
    int e = blockIdx.x * blockDim.x + threadIdx.x;
    if (e >= E_TOT) return;
    int d = (e < E_EDGES) ? ei[E_EDGES + e] : (e - E_EDGES);
    atomicAdd(&cnt[d], 1);
}

__global__ void scan_kernel(const int* __restrict__ cnt,
                            int* __restrict__ offsets,
                            int* __restrict__ cursor) {
    __shared__ int part[1024];
    const int T = 1024;
    const int C = (N_NODES + T - 1) / T;   // 49
    int t = threadIdx.x;
    int lo = t * C;
    int hi = lo + C; if (hi > N_NODES) hi = N_NODES;
    int s = 0;
    for (int i = lo; i < hi; i++) s += cnt[i];
    part[t] = s;
    __syncthreads();
    for (int off = 1; off < T; off <<= 1) {
        int v = (t >= off) ? part[t - off] : 0;
        __syncthreads();
        part[t] += v;
        __syncthreads();
    }
    int run = (t > 0) ? part[t - 1] : 0;   // exclusive base
    for (int i = lo; i < hi; i++) {
        offsets[i] = run;
        cursor[i]  = run;
        run += cnt[i];
    }
    if (t == 0) offsets[N_NODES] = E_TOT;
}

__global__ void scatter_kernel(const int* __restrict__ ei,
                               int* __restrict__ cursor,
                               int* __restrict__ csr_src) {
    int e = blockIdx.x * blockDim.x + threadIdx.x;
    if (e >= E_TOT) return;
    int s, d;
    if (e < E_EDGES) { s = ei[e]; d = ei[E_EDGES + e]; }
    else             { s = d = e - E_EDGES; }
    int pos = atomicAdd(&cursor[d], 1);
    csr_src[pos] = s;
}

// ---------------- tf32 helpers ----------------
__device__ __forceinline__ float tf32r(float x) {
    float r;
    asm("cvt.rna.tf32.f32 %0, %1;" : "=f"(r) : "f"(x));
    return r;
}

__device__ __forceinline__ void mma_tf32(float& c0, float& c1, float& c2, float& c3,
                                         unsigned a0, unsigned a1, unsigned a2, unsigned a3,
                                         unsigned b0, unsigned b1) {
    asm volatile(
        "mma.sync.aligned.m16n8k8.row.col.f32.tf32.tf32.f32 "
        "{%0,%1,%2,%3}, {%4,%5,%6,%7}, {%8,%9}, {%0,%1,%2,%3};"
        : "+f"(c0), "+f"(c1), "+f"(c2), "+f"(c3)
        : "r"(a0), "r"(a1), "r"(a2), "r"(a3), "r"(b0), "r"(b1));
}

// ---------------- GEMM (tf32x3 tensor cores): H = act(X + bias) @ W ----------------
// Block: 256 threads (8 warps), 128 rows. Warp w -> rows 16w..16w+15, all MO cols.
// X tile staged in smem (stride 132 -> conflict-free fragment LDS).
// Each fp32 operand split a = ah + al (tf32); accumulate ah*wh + ah*wl + al*wh.
template<int MO>
__global__ void __launch_bounds__(256)
gemm_mma(const float* __restrict__ X,
         const float* __restrict__ W,
         const float* __restrict__ bias,
         float* __restrict__ Hout) {
    constexpr int XS = 132;                      // float stride per row
    constexpr int NT = MO / 8;                   // n-tiles per warp
    __shared__ float Xs[128 * XS];

    const int tid  = threadIdx.x;
    const int wid  = tid >> 5;
    const int lane = tid & 31;
    const int gp   = lane >> 2;                  // group 0..7
    const int t4   = lane & 3;                   // 0..3
    const int row0 = blockIdx.x * 128;

    // ---- stage X tile (with fused relu(x+bias) of previous layer) ----
#pragma unroll
    for (int it = 0; it < 16; it++) {
        int idx = tid + it * 256;                // 0..4095
        int r  = idx >> 5;
        int k4 = idx & 31;
        int n  = row0 + r;
        float4 v = make_float4(0.f, 0.f, 0.f, 0.f);
        if (n < N_NODES) {
            v = reinterpret_cast<const float4*>(X)[n * 32 + k4];
            if (bias) {
                float4 b = reinterpret_cast<const float4*>(bias)[k4];
                v.x = fmaxf(v.x + b.x, 0.f);
                v.y = fmaxf(v.y + b.y, 0.f);
                v.z = fmaxf(v.z + b.z, 0.f);
                v.w = fmaxf(v.w + b.w, 0.f);
            }
        }
        *reinterpret_cast<float4*>(&Xs[r * XS + 4 * k4]) = v;
    }
    __syncthreads();

    float c[NT][4];
#pragma unroll
    for (int nt = 0; nt < NT; nt++)
#pragma unroll
        for (int j = 0; j < 4; j++) c[nt][j] = 0.f;

    const int ra = wid * 16 + gp;                // fragment rows
    const int rb = ra + 8;

    for (int kt = 0; kt < 16; kt++) {
        int k0 = kt * 8;
        float a0 = Xs[ra * XS + k0 + t4];
        float a1 = Xs[rb * XS + k0 + t4];
        float a2 = Xs[ra * XS + k0 + t4 + 4];
        float a3 = Xs[rb * XS + k0 + t4 + 4];
        float ah0 = tf32r(a0), ah1 = tf32r(a1), ah2 = tf32r(a2), ah3 = tf32r(a3);
        float al0 = tf32r(a0 - ah0), al1 = tf32r(a1 - ah1);
        float al2 = tf32r(a2 - ah2), al3 = tf32r(a3 - ah3);
        unsigned uah0 = __float_as_uint(ah0), uah1 = __float_as_uint(ah1);
        unsigned uah2 = __float_as_uint(ah2), uah3 = __float_as_uint(ah3);
        unsigned ual0 = __float_as_uint(al0), ual1 = __float_as_uint(al1);
        unsigned ual2 = __float_as_uint(al2), ual3 = __float_as_uint(al3);

#pragma unroll
        for (int nt = 0; nt < NT; nt++) {
            int n0 = nt * 8;
            float w0 = W[(k0 + t4) * MO + n0 + gp];
            float w1 = W[(k0 + t4 + 4) * MO + n0 + gp];
            float wh0 = tf32r(w0), wh1 = tf32r(w1);
            float wl0 = tf32r(w0 - wh0), wl1 = tf32r(w1 - wh1);
            unsigned uwh0 = __float_as_uint(wh0), uwh1 = __float_as_uint(wh1);
            unsigned uwl0 = __float_as_uint(wl0), uwl1 = __float_as_uint(wl1);

            mma_tf32(c[nt][0], c[nt][1], c[nt][2], c[nt][3],
                     uah0, uah1, uah2, uah3, uwh0, uwh1);
            mma_tf32(c[nt][0], c[nt][1], c[nt][2], c[nt][3],
                     uah0, uah1, uah2, uah3, uwl0, uwl1);
            mma_tf32(c[nt][0], c[nt][1], c[nt][2], c[nt][3],
                     ual0, ual1, ual2, ual3, uwh0, uwh1);
        }
    }

    // ---- store: c0,c1 -> (ra, n0+2*t4, +1); c2,c3 -> (rb, ...) ----
    int na = row0 + ra;
    int nb = row0 + rb;
#pragma unroll
    for (int nt = 0; nt < NT; nt++) {
        int colb = nt * 8 + 2 * t4;
        if (na < N_NODES)
            *reinterpret_cast<float2*>(&Hout[na * MO + colb]) =
                make_float2(c[nt][0], c[nt][1]);
        if (nb < N_NODES)
            *reinterpret_cast<float2*>(&Hout[nb * MO + colb]) =
                make_float2(c[nt][2], c[nt][3]);
    }
}

// ---------------- attention coefficients ----------------
template<int H, int F>
__global__ void coef_kernel(const float* __restrict__ Hfeat,
                            const float* __restrict__ a_src,
                            const float* __restrict__ a_dst,
                            float* __restrict__ als, float* __restrict__ ald) {
    int i = blockIdx.x * blockDim.x + threadIdx.x;   // n*H + h
    if (i >= N_NODES * H) return;
    int n = i / H, h = i % H;
    const float* hp = Hfeat + n * (H * F) + h * F;
    const float* as = a_src + h * F;
    const float* ad = a_dst + h * F;
    float s = 0.f, d = 0.f;
#pragma unroll 8
    for (int f = 0; f < F; f++) {
        float v = hp[f];
        s = fmaf(v, as[f], s);
        d = fmaf(v, ad[f], d);
    }
    als[i] = s;
    ald[i] = d;
}

// ---------------- fused attention softmax + gather (H=4, F=32) ----------------
__global__ void gather4_kernel(const int* __restrict__ offsets,
                               const int* __restrict__ csr_src,
                               const float* __restrict__ als,
                               const float* __restrict__ ald,
                               const float* __restrict__ Hfeat,
                               float4* __restrict__ p_csr,
                               float* __restrict__ O) {
    int warp = (blockIdx.x * blockDim.x + threadIdx.x) >> 5;
    int lane = threadIdx.x & 31;
    if (warp >= N_NODES) return;
    const int d = warp;
    const int start = offsets[d], end = offsets[d + 1];

    float4 aldv = reinterpret_cast<const float4*>(ald)[d];
    float dx = 0.f, dy = 0.f, dz = 0.f, dw = 0.f;
    for (int j = start + lane; j < end; j += 32) {
        int s = csr_src[j];
        float4 a = reinterpret_cast<const float4*>(als)[s];
        float ex = a.x + aldv.x; ex = (ex > 0.f) ? ex : SLOPE * ex; ex = __expf(ex);
        float ey = a.y + aldv.y; ey = (ey > 0.f) ? ey : SLOPE * ey; ey = __expf(ey);
        float ez = a.z + aldv.z; ez = (ez > 0.f) ? ez : SLOPE * ez; ez = __expf(ez);
        float ew = a.w + aldv.w; ew = (ew > 0.f) ? ew : SLOPE * ew; ew = __expf(ew);
        p_csr[j] = make_float4(ex, ey, ez, ew);
        dx += ex; dy += ey; dz += ez; dw += ew;
    }
#pragma unroll
    for (int o = 16; o > 0; o >>= 1) {
        dx += __shfl_xor_sync(0xffffffffu, dx, o);
        dy += __shfl_xor_sync(0xffffffffu, dy, o);
        dz += __shfl_xor_sync(0xffffffffu, dz, o);
        dw += __shfl_xor_sync(0xffffffffu, dw, o);
    }
    const int h = lane >> 3;                       // head for this lane's float4
    float den = (h == 0) ? dx : (h == 1) ? dy : (h == 2) ? dz : dw;
    float invd = __fdividef(1.f, den);

    const float* ps = reinterpret_cast<const float*>(p_csr);
    float4 acc = make_float4(0.f, 0.f, 0.f, 0.f);
#pragma unroll 4
    for (int j = start; j < end; j++) {
        int s = csr_src[j];                        // broadcast
        float alpha = ps[j * 4 + h] * invd;
        float4 hv = reinterpret_cast<const float4*>(Hfeat)[s * 32 + lane];
        acc.x = fmaf(hv.x, alpha, acc.x);
        acc.y = fmaf(hv.y, alpha, acc.y);
        acc.z = fmaf(hv.z, alpha, acc.z);
        acc.w = fmaf(hv.w, alpha, acc.w);
    }
    reinterpret_cast<float4*>(O)[d * 32 + lane] = acc;
}

// ---------------- fused attention softmax + gather (H=1, F=64) ----------------
__global__ void gather1_kernel(const int* __restrict__ offsets,
                               const int* __restrict__ csr_src,
                               const float* __restrict__ als,
                               const float* __restrict__ ald,
                               const float* __restrict__ Hfeat,
                               float* __restrict__ p_csr,
                               float* __restrict__ O) {
    int warp = (blockIdx.x * blockDim.x + threadIdx.x) >> 5;
    int lane = threadIdx.x & 31;
    if (warp >= N_NODES) return;
    const int d = warp;
    const int start = offsets[d], end = offsets[d + 1];

    float aldd = ald[d];
    float den = 0.f;
    for (int j = start + lane; j < end; j += 32) {
        int s = csr_src[j];
        float e = als[s] + aldd;
        e = (e > 0.f) ? e : SLOPE * e;
        e = __expf(e);
        p_csr[j] = e;
        den += e;
    }
#pragma unroll
    for (int o = 16; o > 0; o >>= 1) den += __shfl_xor_sync(0xffffffffu, den, o);
    float invd = __fdividef(1.f, den);

    float2 acc = make_float2(0.f, 0.f);
#pragma unroll 4
    for (int j = start; j < end; j++) {
        int s = csr_src[j];
        float alpha = p_csr[j] * invd;
        float2 hv = reinterpret_cast<const float2*>(Hfeat)[s * 32 + lane];
        acc.x = fmaf(hv.x, alpha, acc.x);
        acc.y = fmaf(hv.y, alpha, acc.y);
    }
    reinterpret_cast<float2*>(O)[d * 32 + lane] = acc;
}

// ---------------- final: log_softmax(O + b3) over 64 classes ----------------
__global__ void final_kernel(const float* __restrict__ O,
                             const float* __restrict__ b3,
                             float* __restrict__ out) {
    int warp = (blockIdx.x * blockDim.x + threadIdx.x) >> 5;
    int lane = threadIdx.x & 31;
    if (warp >= N_NODES) return;
    const float* row = O + warp * 64;
    float v0 = row[lane]      + b3[lane];
    float v1 = row[32 + lane] + b3[32 + lane];
    float mx = fmaxf(v0, v1);
#pragma unroll
    for (int o = 16; o > 0; o >>= 1) mx = fmaxf(mx, __shfl_xor_sync(0xffffffffu, mx, o));
    float se = expf(v0 - mx) + expf(v1 - mx);
#pragma unroll
    for (int o = 16; o > 0; o >>= 1) se += __shfl_xor_sync(0xffffffffu, se, o);
    float lse = mx + logf(se);
    out[warp * 64 + lane]      = v0 - lse;
    out[warp * 64 + 32 + lane] = v1 - lse;
}

// ---------------- launcher ----------------
extern "C" void kernel_launch(void* const* d_in, const int* in_sizes, int n_in,
                              void* d_out, int out_size) {
    const float* x   = (const float*)d_in[0];
    const int*   ei  = (const int*)  d_in[1];
    const float* w1  = (const float*)d_in[2];
    const float* as1 = (const float*)d_in[3];
    const float* ad1 = (const float*)d_in[4];
    const float* b1  = (const float*)d_in[5];
    const float* w2  = (const float*)d_in[6];
    const float* as2 = (const float*)d_in[7];
    const float* ad2 = (const float*)d_in[8];
    const float* b2  = (const float*)d_in[9];
    const float* w3  = (const float*)d_in[10];
    const float* as3 = (const float*)d_in[11];
    const float* ad3 = (const float*)d_in[12];
    const float* b3  = (const float*)d_in[13];
    float* out = (float*)d_out;

    float *hbuf, *obuf, *als, *ald, *pbuf;
    int *cnt, *off, *cur, *csrc;
    cudaGetSymbolAddress((void**)&hbuf, g_h);
    cudaGetSymbolAddress((void**)&obuf, g_o);
    cudaGetSymbolAddress((void**)&als,  g_als);
    cudaGetSymbolAddress((void**)&ald,  g_ald);
    cudaGetSymbolAddress((void**)&pbuf, g_p);
    cudaGetSymbolAddress((void**)&cnt,  g_cnt);
    cudaGetSymbolAddress((void**)&off,  g_off);
    cudaGetSymbolAddress((void**)&cur,  g_cur);
    cudaGetSymbolAddress((void**)&csrc, g_csrc);

    auto cdiv = [](long long a, long long b) { return (int)((a + b - 1) / b); };

    const int gatherGrid = cdiv((long long)N_NODES * 32, 256);
    const int gemmGrid = cdiv(N_NODES, 128);   // 391

    // ---- fork: CSR build on side stream, concurrent with layer-1 GEMM+coef ----
    cudaEventRecord(g_ss.fork, 0);
    cudaStreamWaitEvent(g_ss.s, g_ss.fork, 0);
    zero_int_kernel<<<cdiv(N_NODES, 256), 256, 0, g_ss.s>>>(cnt, N_NODES);
    hist_kernel<<<cdiv(E_TOT, 256), 256, 0, g_ss.s>>>(ei, cnt);
    scan_kernel<<<1, 1024, 0, g_ss.s>>>(cnt, off, cur);
    scatter_kernel<<<cdiv(E_TOT, 256), 256, 0, g_ss.s>>>(ei, cur, csrc);
    cudaEventRecord(g_ss.join, g_ss.s);

    // ---- layer 1 (main stream, overlaps CSR build) ----
    gemm_mma<128><<<gemmGrid, 256>>>(x, w1, nullptr, hbuf);
    coef_kernel<4, 32><<<cdiv(N_NODES * 4, 256), 256>>>(hbuf, as1, ad1, als, ald);
    cudaStreamWaitEvent(0, g_ss.join, 0);          // join before gather
    gather4_kernel<<<gatherGrid, 256>>>(off, csrc, als, ald, hbuf,
                                        (float4*)pbuf, obuf);

    // ---- layer 2 ----
    gemm_mma<128><<<gemmGrid, 256>>>(obuf, w2, b1, hbuf);
    coef_kernel<4, 32><<<cdiv(N_NODES * 4, 256), 256>>>(hbuf, as2, ad2, als, ald);
    gather4_kernel<<<gatherGrid, 256>>>(off, csrc, als, ald, hbuf,
                                        (float4*)pbuf, obuf);

    // ---- layer 3 ----
    gemm_mma<64><<<gemmGrid, 256>>>(obuf, w3, b2, hbuf);
    coef_kernel<1, 64><<<cdiv(N_NODES, 256), 256>>>(hbuf, as3, ad3, als, ald);
    gather1_kernel<<<gatherGrid, 256>>>(off, csrc, als, ald, hbuf, pbuf, obuf);

    // ---- log_softmax ----
    final_kernel<<<gatherGrid, 256>>>(obuf, b3, out);
}

// round 8
// speedup vs baseline: 1.9250x; 1.2995x over previous
#include <cuda_runtime.h>
#include <math.h>

#define N_NODES 50000
#define E_EDGES 800000
#define E_TOT   (E_EDGES + N_NODES)   // 850000 with self loops
#define F_IN    128
#define SLOPE   0.2f

// ---------------- scratch (static __device__ — no allocation) ----------------
__device__ float g_h[N_NODES * 128];        // transformed features
__device__ float g_o[N_NODES * 128];        // aggregated output
__device__ float g_als[N_NODES * 4];
__device__ float g_ald[N_NODES * 4];
__device__ float g_p[E_TOT * 4];            // exp(e) per edge (CSR order)
__device__ int   g_cnt[N_NODES];
__device__ int   g_off[N_NODES + 1];
__device__ int   g_cur[N_NODES];
__device__ int   g_csrc[E_TOT];

// ---------------- CSR build ----------------
__global__ void zero_int_kernel(int* p, int n) {
    int i = blockIdx.x * blockDim.x + threadIdx.x;
    if (i < n) p[i] = 0;
}

__global__ void hist_kernel(const int* __restrict__ ei, int* __restrict__ cnt) {
    int e = blockIdx.x * blockDim.x + threadIdx.x;
    if (e >= E_TOT) return;
    int d = (e < E_EDGES) ? ei[E_EDGES + e] : (e - E_EDGES);
    atomicAdd(&cnt[d], 1);
}

__global__ void scan_kernel(const int* __restrict__ cnt,
                            int* __restrict__ offsets,
                            int* __restrict__ cursor) {
    __shared__ int part[1024];
    const int T = 1024;
    const int C = (N_NODES + T - 1) / T;   // 49
    int t = threadIdx.x;
    int lo = t * C;
    int hi = lo + C; if (hi > N_NODES) hi = N_NODES;
    int s = 0;
    for (int i = lo; i < hi; i++) s += cnt[i];
    part[t] = s;
    __syncthreads();
    for (int off = 1; off < T; off <<= 1) {
        int v = (t >= off) ? part[t - off] : 0;
        __syncthreads();
        part[t] += v;
        __syncthreads();
    }
    int run = (t > 0) ? part[t - 1] : 0;   // exclusive base
    for (int i = lo; i < hi; i++) {
        offsets[i] = run;
        cursor[i]  = run;
        run += cnt[i];
    }
    if (t == 0) offsets[N_NODES] = E_TOT;
}

__global__ void scatter_kernel(const int* __restrict__ ei,
                               int* __restrict__ cursor,
                               int* __restrict__ csr_src) {
    int e = blockIdx.x * blockDim.x + threadIdx.x;
    if (e >= E_TOT) return;
    int s, d;
    if (e < E_EDGES) { s = ei[e]; d = ei[E_EDGES + e]; }
    else             { s = d = e - E_EDGES; }
    int pos = atomicAdd(&cursor[d], 1);
    csr_src[pos] = s;
}

// ---------------- tf32 helpers ----------------
__device__ __forceinline__ float tf32r(float x) {
    float r;
    asm("cvt.rna.tf32.f32 %0, %1;" : "=f"(r) : "f"(x));
    return r;
}

__device__ __forceinline__ void mma_tf32(float& c0, float& c1, float& c2, float& c3,
                                         unsigned a0, unsigned a1, unsigned a2, unsigned a3,
                                         unsigned b0, unsigned b1) {
    asm volatile(
        "mma.sync.aligned.m16n8k8.row.col.f32.tf32.tf32.f32 "
        "{%0,%1,%2,%3}, {%4,%5,%6,%7}, {%8,%9}, {%0,%1,%2,%3};"
        : "+f"(c0), "+f"(c1), "+f"(c2), "+f"(c3)
        : "r"(a0), "r"(a1), "r"(a2), "r"(a3), "r"(b0), "r"(b1));
}

// ---------------- GEMM (tf32x3) + fused attention-coef epilogue ----------------
// Block: 256 threads (8 warps), 128 rows. Warp w -> rows 16w..16w+15, all MO cols.
// W k-slices staged in smem (tf32 hi/lo split done once cooperatively).
// Epilogue computes als/ald per row via lane-quad shfl reduction.
template<int MO, int H>
__global__ void __launch_bounds__(256)
gemm_mma(const float* __restrict__ X,
         const float* __restrict__ W,
         const float* __restrict__ bias,
         const float* __restrict__ a_src,
         const float* __restrict__ a_dst,
         float* __restrict__ Hout,
         float* __restrict__ als,
         float* __restrict__ ald) {
    constexpr int XS = 132;                      // X row stride (banks: 4gp+t4 distinct)
    constexpr int WS = MO + 8;                   // 136 / 72 -> WS % 32 == 8
    constexpr int NT = MO / 8;                   // n-tiles per warp

    extern __shared__ float smem_f[];
    float* Xs  = smem_f;                         // 128 * XS
    float* Whi = Xs + 128 * XS;                  // 8 * WS
    float* Wlo = Whi + 8 * WS;                   // 8 * WS

    const int tid  = threadIdx.x;
    const int wid  = tid >> 5;
    const int lane = tid & 31;
    const int gp   = lane >> 2;                  // group 0..7
    const int t4   = lane & 3;                   // 0..3
    const int row0 = blockIdx.x * 128;

    // ---- stage X tile (with fused relu(x+bias) of previous layer) ----
#pragma unroll
    for (int it = 0; it < 16; it++) {
        int idx = tid + it * 256;                // 0..4095
        int r  = idx >> 5;
        int k4 = idx & 31;
        int n  = row0 + r;
        float4 v = make_float4(0.f, 0.f, 0.f, 0.f);
        if (n < N_NODES) {
            v = reinterpret_cast<const float4*>(X)[n * 32 + k4];
            if (bias) {
                float4 b = reinterpret_cast<const float4*>(bias)[k4];
                v.x = fmaxf(v.x + b.x, 0.f);
                v.y = fmaxf(v.y + b.y, 0.f);
                v.z = fmaxf(v.z + b.z, 0.f);
                v.w = fmaxf(v.w + b.w, 0.f);
            }
        }
        *reinterpret_cast<float4*>(&Xs[r * XS + 4 * k4]) = v;
    }

    float c[NT][4];
#pragma unroll
    for (int nt = 0; nt < NT; nt++)
#pragma unroll
        for (int j = 0; j < 4; j++) c[nt][j] = 0.f;

    const int ra = wid * 16 + gp;                // fragment rows
    const int rb = ra + 8;

    for (int kt = 0; kt < 16; kt++) {
        int k0 = kt * 8;
        __syncthreads();                         // finish prior reads (and Xs stores)
        // ---- stage W slice [k0..k0+8) x MO, tf32 split, cooperatively ----
        for (int i = tid * 4; i < 8 * MO; i += 1024) {
            int r = i / MO, cc = i % MO;
            float4 w = *reinterpret_cast<const float4*>(&W[(k0 + r) * MO + cc]);
            float4 hi, lo;
            hi.x = tf32r(w.x); lo.x = tf32r(w.x - hi.x);
            hi.y = tf32r(w.y); lo.y = tf32r(w.y - hi.y);
            hi.z = tf32r(w.z); lo.z = tf32r(w.z - hi.z);
            hi.w = tf32r(w.w); lo.w = tf32r(w.w - hi.w);
            *reinterpret_cast<float4*>(&Whi[r * WS + cc]) = hi;
            *reinterpret_cast<float4*>(&Wlo[r * WS + cc]) = lo;
        }
        __syncthreads();

        // ---- A fragments ----
        float a0 = Xs[ra * XS + k0 + t4];
        float a1 = Xs[rb * XS + k0 + t4];
        float a2 = Xs[ra * XS + k0 + t4 + 4];
        float a3 = Xs[rb * XS + k0 + t4 + 4];
        float ah0 = tf32r(a0), ah1 = tf32r(a1), ah2 = tf32r(a2), ah3 = tf32r(a3);
        float al0 = tf32r(a0 - ah0), al1 = tf32r(a1 - ah1);
        float al2 = tf32r(a2 - ah2), al3 = tf32r(a3 - ah3);
        unsigned uah0 = __float_as_uint(ah0), uah1 = __float_as_uint(ah1);
        unsigned uah2 = __float_as_uint(ah2), uah3 = __float_as_uint(ah3);
        unsigned ual0 = __float_as_uint(al0), ual1 = __float_as_uint(al1);
        unsigned ual2 = __float_as_uint(al2), ual3 = __float_as_uint(al3);

#pragma unroll
        for (int nt = 0; nt < NT; nt++) {
            int n0 = nt * 8;
            unsigned uwh0 = __float_as_uint(Whi[t4 * WS + n0 + gp]);
            unsigned uwh1 = __float_as_uint(Whi[(t4 + 4) * WS + n0 + gp]);
            unsigned uwl0 = __float_as_uint(Wlo[t4 * WS + n0 + gp]);
            unsigned uwl1 = __float_as_uint(Wlo[(t4 + 4) * WS + n0 + gp]);

            mma_tf32(c[nt][0], c[nt][1], c[nt][2], c[nt][3],
                     uah0, uah1, uah2, uah3, uwh0, uwh1);
            mma_tf32(c[nt][0], c[nt][1], c[nt][2], c[nt][3],
                     uah0, uah1, uah2, uah3, uwl0, uwl1);
            mma_tf32(c[nt][0], c[nt][1], c[nt][2], c[nt][3],
                     ual0, ual1, ual2, ual3, uwh0, uwh1);
        }
    }

    // ---- store H ----
    int na = row0 + ra;
    int nb = row0 + rb;
#pragma unroll
    for (int nt = 0; nt < NT; nt++) {
        int colb = nt * 8 + 2 * t4;
        if (na < N_NODES)
            *reinterpret_cast<float2*>(&Hout[na * MO + colb]) =
                make_float2(c[nt][0], c[nt][1]);
        if (nb < N_NODES)
            *reinterpret_cast<float2*>(&Hout[nb * MO + colb]) =
                make_float2(c[nt][2], c[nt][3]);
    }

    // ---- fused coef epilogue: als/ald per row via lane-quad reduction ----
    float sA[H], dA[H], sB[H], dB[H];
#pragma unroll
    for (int h = 0; h < H; h++) { sA[h] = dA[h] = sB[h] = dB[h] = 0.f; }
#pragma unroll
    for (int nt = 0; nt < NT; nt++) {
        int c0 = nt * 8 + 2 * t4;
        float2 as2 = *reinterpret_cast<const float2*>(&a_src[c0]);
        float2 ad2 = *reinterpret_cast<const float2*>(&a_dst[c0]);
        int h = (H == 4) ? (nt >> 2) : 0;
        sA[h] = fmaf(c[nt][0], as2.x, fmaf(c[nt][1], as2.y, sA[h]));
        dA[h] = fmaf(c[nt][0], ad2.x, fmaf(c[nt][1], ad2.y, dA[h]));
        sB[h] = fmaf(c[nt][2], as2.x, fmaf(c[nt][3], as2.y, sB[h]));
        dB[h] = fmaf(c[nt][2], ad2.x, fmaf(c[nt][3], ad2.y, dB[h]));
    }
#pragma unroll
    for (int h = 0; h < H; h++) {
        sA[h] += __shfl_xor_sync(0xffffffffu, sA[h], 1);
        sA[h] += __shfl_xor_sync(0xffffffffu, sA[h], 2);
        dA[h] += __shfl_xor_sync(0xffffffffu, dA[h], 1);
        dA[h] += __shfl_xor_sync(0xffffffffu, dA[h], 2);
        sB[h] += __shfl_xor_sync(0xffffffffu, sB[h], 1);
        sB[h] += __shfl_xor_sync(0xffffffffu, sB[h], 2);
        dB[h] += __shfl_xor_sync(0xffffffffu, dB[h], 1);
        dB[h] += __shfl_xor_sync(0xffffffffu, dB[h], 2);
    }
    if (H == 4) {
        int h = t4;
        if (na < N_NODES) { als[na * 4 + h] = sA[h]; ald[na * 4 + h] = dA[h]; }
        if (nb < N_NODES) { als[nb * 4 + h] = sB[h]; ald[nb * 4 + h] = dB[h]; }
    } else {
        if (t4 == 0) {
            if (na < N_NODES) { als[na] = sA[0]; ald[na] = dA[0]; }
            if (nb < N_NODES) { als[nb] = sB[0]; ald[nb] = dB[0]; }
        }
    }
}

constexpr int SMEM_G128 = (128 * 132 + 2 * 8 * 136) * 4;   // 76288
constexpr int SMEM_G64  = (128 * 132 + 2 * 8 * 72) * 4;    // 72192

// ---------------- side stream + kernel attrs (program-load init) ----------------
struct Setup {
    cudaStream_t s;
    cudaEvent_t fork, join;
    Setup() {
        cudaStreamCreateWithFlags(&s, cudaStreamNonBlocking);
        cudaEventCreateWithFlags(&fork, cudaEventDisableTiming);
        cudaEventCreateWithFlags(&join, cudaEventDisableTiming);
        cudaFuncSetAttribute((const void*)&gemm_mma<128, 4>,
                             cudaFuncAttributeMaxDynamicSharedMemorySize, SMEM_G128);
        cudaFuncSetAttribute((const void*)&gemm_mma<64, 1>,
                             cudaFuncAttributeMaxDynamicSharedMemorySize, SMEM_G64);
    }
};
static Setup g_ss;

// ---------------- fused attention softmax + gather (H=4, F=32) ----------------
__global__ void gather4_kernel(const int* __restrict__ offsets,
                               const int* __restrict__ csr_src,
                               const float* __restrict__ als,
                               const float* __restrict__ ald,
                               const float* __restrict__ Hfeat,
                               float4* __restrict__ p_csr,
                               float* __restrict__ O) {
    int warp = (blockIdx.x * blockDim.x + threadIdx.x) >> 5;
    int lane = threadIdx.x & 31;
    if (warp >= N_NODES) return;
    const int d = warp;
    const int start = offsets[d], end = offsets[d + 1];

    float4 aldv = reinterpret_cast<const float4*>(ald)[d];
    float dx = 0.f, dy = 0.f, dz = 0.f, dw = 0.f;
    for (int j = start + lane; j < end; j += 32) {
        int s = csr_src[j];
        float4 a = reinterpret_cast<const float4*>(als)[s];
        float ex = a.x + aldv.x; ex = (ex > 0.f) ? ex : SLOPE * ex; ex = __expf(ex);
        float ey = a.y + aldv.y; ey = (ey > 0.f) ? ey : SLOPE * ey; ey = __expf(ey);
        float ez = a.z + aldv.z; ez = (ez > 0.f) ? ez : SLOPE * ez; ez = __expf(ez);
        float ew = a.w + aldv.w; ew = (ew > 0.f) ? ew : SLOPE * ew; ew = __expf(ew);
        p_csr[j] = make_float4(ex, ey, ez, ew);
        dx += ex; dy += ey; dz += ez; dw += ew;
    }
#pragma unroll
    for (int o = 16; o > 0; o >>= 1) {
        dx += __shfl_xor_sync(0xffffffffu, dx, o);
        dy += __shfl_xor_sync(0xffffffffu, dy, o);
        dz += __shfl_xor_sync(0xffffffffu, dz, o);
        dw += __shfl_xor_sync(0xffffffffu, dw, o);
    }
    const int h = lane >> 3;                       // head for this lane's float4
    float den = (h == 0) ? dx : (h == 1) ? dy : (h == 2) ? dz : dw;
    float invd = __fdividef(1.f, den);

    const float* ps = reinterpret_cast<const float*>(p_csr);
    float4 acc = make_float4(0.f, 0.f, 0.f, 0.f);
#pragma unroll 4
    for (int j = start; j < end; j++) {
        int s = csr_src[j];                        // broadcast
        float alpha = ps[j * 4 + h] * invd;
        float4 hv = reinterpret_cast<const float4*>(Hfeat)[s * 32 + lane];
        acc.x = fmaf(hv.x, alpha, acc.x);
        acc.y = fmaf(hv.y, alpha, acc.y);
        acc.z = fmaf(hv.z, alpha, acc.z);
        acc.w = fmaf(hv.w, alpha, acc.w);
    }
    reinterpret_cast<float4*>(O)[d * 32 + lane] = acc;
}

// ---------------- fused gather (H=1,F=64) + bias + log_softmax ----------------
__global__ void gather1_final(const int* __restrict__ offsets,
                              const int* __restrict__ csr_src,
                              const float* __restrict__ als,
                              const float* __restrict__ ald,
                              const float* __restrict__ Hfeat,
                              float* __restrict__ p_csr,
                              const float* __restrict__ b3,
                              float* __restrict__ out) {
    int warp = (blockIdx.x * blockDim.x + threadIdx.x) >> 5;
    int lane = threadIdx.x & 31;
    if (warp >= N_NODES) return;
    const int d = warp;
    const int start = offsets[d], end = offsets[d + 1];

    float aldd = ald[d];
    float den = 0.f;
    for (int j = start + lane; j < end; j += 32) {
        int s = csr_src[j];
        float e = als[s] + aldd;
        e = (e > 0.f) ? e : SLOPE * e;
        e = __expf(e);
        p_csr[j] = e;
        den += e;
    }
#pragma unroll
    for (int o = 16; o > 0; o >>= 1) den += __shfl_xor_sync(0xffffffffu, den, o);
    float invd = __fdividef(1.f, den);

    float2 acc = make_float2(0.f, 0.f);
#pragma unroll 4
    for (int j = start; j < end; j++) {
        int s = csr_src[j];
        float alpha = p_csr[j] * invd;
        float2 hv = reinterpret_cast<const float2*>(Hfeat)[s * 32 + lane];
        acc.x = fmaf(hv.x, alpha, acc.x);
        acc.y = fmaf(hv.y, alpha, acc.y);
    }

    // log_softmax over the 64 classes held pairwise across the warp
    float2 b = reinterpret_cast<const float2*>(b3)[lane];
    float v0 = acc.x + b.x;
    float v1 = acc.y + b.y;
    float mx = fmaxf(v0, v1);
#pragma unroll
    for (int o = 16; o > 0; o >>= 1) mx = fmaxf(mx, __shfl_xor_sync(0xffffffffu, mx, o));
    float se = expf(v0 - mx) + expf(v1 - mx);
#pragma unroll
    for (int o = 16; o > 0; o >>= 1) se += __shfl_xor_sync(0xffffffffu, se, o);
    float lse = mx + logf(se);
    reinterpret_cast<float2*>(out)[d * 32 + lane] = make_float2(v0 - lse, v1 - lse);
}

// ---------------- launcher ----------------
extern "C" void kernel_launch(void* const* d_in, const int* in_sizes, int n_in,
                              void* d_out, int out_size) {
    const float* x   = (const float*)d_in[0];
    const int*   ei  = (const int*)  d_in[1];
    const float* w1  = (const float*)d_in[2];
    const float* as1 = (const float*)d_in[3];
    const float* ad1 = (const float*)d_in[4];
    const float* b1  = (const float*)d_in[5];
    const float* w2  = (const float*)d_in[6];
    const float* as2 = (const float*)d_in[7];
    const float* ad2 = (const float*)d_in[8];
    const float* b2  = (const float*)d_in[9];
    const float* w3  = (const float*)d_in[10];
    const float* as3 = (const float*)d_in[11];
    const float* ad3 = (const float*)d_in[12];
    const float* b3  = (const float*)d_in[13];
    float* out = (float*)d_out;

    float *hbuf, *obuf, *als, *ald, *pbuf;
    int *cnt, *off, *cur, *csrc;
    cudaGetSymbolAddress((void**)&hbuf, g_h);
    cudaGetSymbolAddress((void**)&obuf, g_o);
    cudaGetSymbolAddress((void**)&als,  g_als);
    cudaGetSymbolAddress((void**)&ald,  g_ald);
    cudaGetSymbolAddress((void**)&pbuf, g_p);
    cudaGetSymbolAddress((void**)&cnt,  g_cnt);
    cudaGetSymbolAddress((void**)&off,  g_off);
    cudaGetSymbolAddress((void**)&cur,  g_cur);
    cudaGetSymbolAddress((void**)&csrc, g_csrc);

    auto cdiv = [](long long a, long long b) { return (int)((a + b - 1) / b); };

    const int gatherGrid = cdiv((long long)N_NODES * 32, 256);
    const int gemmGrid = cdiv(N_NODES, 128);   // 391

    // ---- fork: CSR build on side stream, concurrent with layer-1 GEMM ----
    cudaEventRecord(g_ss.fork, 0);
    cudaStreamWaitEvent(g_ss.s, g_ss.fork, 0);
    zero_int_kernel<<<cdiv(N_NODES, 256), 256, 0, g_ss.s>>>(cnt, N_NODES);
    hist_kernel<<<cdiv(E_TOT, 256), 256, 0, g_ss.s>>>(ei, cnt);
    scan_kernel<<<1, 1024, 0, g_ss.s>>>(cnt, off, cur);
    scatter_kernel<<<cdiv(E_TOT, 256), 256, 0, g_ss.s>>>(ei, cur, csrc);
    cudaEventRecord(g_ss.join, g_ss.s);

    // ---- layer 1 (main stream, overlaps CSR build) ----
    gemm_mma<128, 4><<<gemmGrid, 256, SMEM_G128>>>(x, w1, nullptr, as1, ad1,
                                                   hbuf, als, ald);
    cudaStreamWaitEvent(0, g_ss.join, 0);          // join before gather
    gather4_kernel<<<gatherGrid, 256>>>(off, csrc, als, ald, hbuf,
                                        (float4*)pbuf, obuf);

    // ---- layer 2 ----
    gemm_mma<128, 4><<<gemmGrid, 256, SMEM_G128>>>(obuf, w2, b1, as2, ad2,
                                                   hbuf, als, ald);
    gather4_kernel<<<gatherGrid, 256>>>(off, csrc, als, ald, hbuf,
                                        (float4*)pbuf, obuf);

    // ---- layer 3 (gather fused with bias + log_softmax) ----
    gemm_mma<64, 1><<<gemmGrid, 256, SMEM_G64>>>(obuf, w3, b2, as3, ad3,
                                                 hbuf, als, ald);
    gather1_final<<<gatherGrid, 256>>>(off, csrc, als, ald, hbuf, pbuf, b3, out);
}